// round 3
// baseline (speedup 1.0000x reference)
#include <cuda_runtime.h>
#include <cstdint>

// cReLU_percent: x (32, 128, 112, 112) fp32, PERCENT=0.5 -> k=64 of C=128.
// Per pixel (n,h,w): t = 64th largest over channels; out = relu(where(x>=t, x, 0)).
// Key fact: let c = #positives. If c < 64 -> t <= 0 -> out = relu(x).
//           If c >= 64 -> t = (c-63)-th smallest positive (exact, via warp min-extraction).

#define FULLMASK 0xffffffffu
#define SENT     0x7FFFFFFFu   // > any finite positive float's bit pattern

__global__ __launch_bounds__(256, 4)
void crelu_percent_kernel(const float* __restrict__ x, float* __restrict__ out) {
    __shared__ float tile[128][33];   // [channel][pixel], +1 pad: conflict-free both phases
    __shared__ float thr_s[32];

    const int tid  = threadIdx.x;
    const int lane = tid & 31;
    const int warp = tid >> 5;

    // Block -> (image n, spatial offset s0). HW = 112*112 = 12544 = 392 * 32.
    const int nblk = blockIdx.x;            // 0 .. 12543
    const int n    = nblk / 392;
    const int s0   = (nblk - n * 392) << 5; // *32
    const int base = n * (128 * 12544) + s0;   // fits in int (max ~51.4M)

    // ---- Load phase: 16 channels per thread, coalesced (lanes = consecutive s) ----
    float v[16];
    #pragma unroll
    for (int i = 0; i < 16; ++i) {
        const int c = warp + (i << 3);                 // c = warp + 8*i
        v[i] = x[base + c * 12544 + lane];
        tile[c][lane] = v[i];
    }
    __syncthreads();

    // ---- Selection phase: each warp handles 4 pixels ----
    for (int pi = 0; pi < 4; ++pi) {
        const int p = (warp << 2) + pi;

        // Each lane gathers 4 channel values of pixel p (conflict-free LDS).
        const float a0 = tile[lane      ][p];
        const float a1 = tile[lane + 32 ][p];
        const float a2 = tile[lane + 64 ][p];
        const float a3 = tile[lane + 96 ][p];

        // Positive floats order-preserve as unsigned ints; non-positives -> sentinel.
        unsigned k0 = (a0 > 0.0f) ? __float_as_uint(a0) : SENT;
        unsigned k1 = (a1 > 0.0f) ? __float_as_uint(a1) : SENT;
        unsigned k2 = (a2 > 0.0f) ? __float_as_uint(a2) : SENT;
        unsigned k3 = (a3 > 0.0f) ? __float_as_uint(a3) : SENT;

        const int cnt = (a0 > 0.0f) + (a1 > 0.0f) + (a2 > 0.0f) + (a3 > 0.0f);
        const int c   = __reduce_add_sync(FULLMASK, cnt);   // # positives in pixel

        float thr = 0.0f;                 // c < 64: threshold <= 0 -> out == relu(x)
        if (c >= 64) {
            const int m = c - 63;         // threshold = m-th smallest positive
            unsigned wmin = 0;
            for (int r = 0; r < m; ++r) {
                const unsigned lmin = min(min(k0, k1), min(k2, k3));
                wmin = __reduce_min_sync(FULLMASK, lmin);   // REDUX.UMIN
                if (r + 1 < m) {
                    // remove exactly one instance of wmin
                    const bool has = (k0 == wmin) || (k1 == wmin) ||
                                     (k2 == wmin) || (k3 == wmin);
                    const unsigned msk = __ballot_sync(FULLMASK, has);
                    if (lane == (__ffs(msk) - 1)) {
                        if      (k0 == wmin) k0 = SENT;
                        else if (k1 == wmin) k1 = SENT;
                        else if (k2 == wmin) k2 = SENT;
                        else                 k3 = SENT;
                    }
                }
            }
            thr = __uint_as_float(wmin);
        }
        if (lane == 0) thr_s[p] = thr;
    }
    __syncthreads();

    // ---- Output phase: values still in registers; threshold broadcast from smem ----
    const float t = thr_s[lane];
    #pragma unroll
    for (int i = 0; i < 16; ++i) {
        const int c = warp + (i << 3);
        const float val = v[i];
        float r = (val >= t) ? val : 0.0f;
        r = fmaxf(r, 0.0f);
        out[base + c * 12544 + lane] = r;
    }
}

extern "C" void kernel_launch(void* const* d_in, const int* in_sizes, int n_in,
                              void* d_out, int out_size) {
    const float* x = (const float*)d_in[0];
    float* out = (float*)d_out;
    // 32 images * (12544/32 = 392) spatial tiles = 12544 blocks, 256 threads each.
    crelu_percent_kernel<<<12544, 256>>>(x, out);
}

// round 6
// speedup vs baseline: 1.0206x; 1.0206x over previous
#include <cuda_runtime.h>
#include <cstdint>

// cReLU_percent: x (32, 128, 112, 112) fp32, PERCENT=0.5 -> k=64 of C=128.
// Per pixel (n,h,w): t = 64th largest over channels; out = relu(where(x>=t, x, 0)).
// Key fact: let c = #positives. If c < 64 -> t <= 0 -> out = relu(x).
//           If c >= 64 -> t = (c-63)-th smallest positive (exact, via warp min-extraction).
// R3: vectorize GMEM to LDG.128/STG.128 (4x fewer mem instructions) to unbind issue.

#define FULLMASK 0xffffffffu
#define SENT     0x7FFFFFFFu   // > any finite positive float's bit pattern

__global__ __launch_bounds__(256, 4)
void crelu_percent_kernel(const float* __restrict__ x, float* __restrict__ out) {
    __shared__ float tile[128][33];   // [channel][pixel], +1 pad: conflict-free both phases
    __shared__ float thr_s[32];

    const int tid  = threadIdx.x;
    const int lane = tid & 31;
    const int warp = tid >> 5;

    // Block -> (image n, spatial offset s0). HW = 112*112 = 12544 = 392 * 32.
    const int nblk = blockIdx.x;            // 0 .. 12543
    const int n    = nblk / 392;
    const int s0   = (nblk - n * 392) << 5; // *32
    const int base = n * (128 * 12544) + s0;   // fits in int (max ~51.4M)

    // ---- Load phase: 4 float4 per thread, coalesced (8 lanes cover one 128B row half) ----
    // float4 id F = tid + 256*i: ch = F>>3 = (tid>>3) + 32*i, group g = tid&7 (4 pixels).
    const int g   = tid & 7;           // pixel quad within the 32-pixel tile
    const int ch0 = tid >> 3;          // base channel (0..31), +32*i
    float4 v[4];
    #pragma unroll
    for (int i = 0; i < 4; ++i) {
        const int c = ch0 + (i << 5);
        v[i] = *reinterpret_cast<const float4*>(x + base + c * 12544 + (g << 2));
        // STS.32 x4: bank = (c + 4g + j) mod 32 -> distinct across lanes: conflict-free
        tile[c][(g << 2) + 0] = v[i].x;
        tile[c][(g << 2) + 1] = v[i].y;
        tile[c][(g << 2) + 2] = v[i].z;
        tile[c][(g << 2) + 3] = v[i].w;
    }
    __syncthreads();

    // ---- Selection phase: each warp handles 4 pixels ----
    #pragma unroll
    for (int pi = 0; pi < 4; ++pi) {
        const int p = (warp << 2) + pi;

        // Each lane gathers 4 channel values of pixel p (conflict-free: bank = lane+p).
        const float a0 = tile[lane      ][p];
        const float a1 = tile[lane + 32 ][p];
        const float a2 = tile[lane + 64 ][p];
        const float a3 = tile[lane + 96 ][p];

        // Positive floats order-preserve as unsigned ints; non-positives -> sentinel.
        unsigned k0 = (a0 > 0.0f) ? __float_as_uint(a0) : SENT;
        unsigned k1 = (a1 > 0.0f) ? __float_as_uint(a1) : SENT;
        unsigned k2 = (a2 > 0.0f) ? __float_as_uint(a2) : SENT;
        unsigned k3 = (a3 > 0.0f) ? __float_as_uint(a3) : SENT;

        const int cnt = (a0 > 0.0f) + (a1 > 0.0f) + (a2 > 0.0f) + (a3 > 0.0f);
        const int c   = __reduce_add_sync(FULLMASK, cnt);   // # positives in pixel

        float thr = 0.0f;                 // c < 64: threshold <= 0 -> out == relu(x)
        if (c >= 64) {
            const int m = c - 63;         // threshold = m-th smallest positive
            unsigned wmin = 0;
            for (int r = 0; r < m; ++r) {
                const unsigned lmin = min(min(k0, k1), min(k2, k3));
                wmin = __reduce_min_sync(FULLMASK, lmin);   // REDUX.UMIN
                if (r + 1 < m) {
                    // remove exactly one instance of wmin (duplicate-safe)
                    const bool has = (k0 == wmin) || (k1 == wmin) ||
                                     (k2 == wmin) || (k3 == wmin);
                    const unsigned msk = __ballot_sync(FULLMASK, has);
                    if (lane == (__ffs(msk) - 1)) {
                        if      (k0 == wmin) k0 = SENT;
                        else if (k1 == wmin) k1 = SENT;
                        else if (k2 == wmin) k2 = SENT;
                        else                 k3 = SENT;
                    }
                }
            }
            thr = __uint_as_float(wmin);
        }
        if (lane == 0) thr_s[p] = thr;
    }
    __syncthreads();

    // ---- Output phase: values still in registers; thresholds via one broadcast LDS.128 ----
    // Threshold t >= +0.0 always, so (v >= t ? v : 0) == relu(where(v >= t_true, v, 0)).
    const float4 tq = *reinterpret_cast<const float4*>(&thr_s[g << 2]);
    #pragma unroll
    for (int i = 0; i < 4; ++i) {
        const int c = ch0 + (i << 5);
        float4 o;
        o.x = (v[i].x >= tq.x) ? v[i].x : 0.0f;
        o.y = (v[i].y >= tq.y) ? v[i].y : 0.0f;
        o.z = (v[i].z >= tq.z) ? v[i].z : 0.0f;
        o.w = (v[i].w >= tq.w) ? v[i].w : 0.0f;
        *reinterpret_cast<float4*>(out + base + c * 12544 + (g << 2)) = o;
    }
}

extern "C" void kernel_launch(void* const* d_in, const int* in_sizes, int n_in,
                              void* d_out, int out_size) {
    const float* x = (const float*)d_in[0];
    float* out = (float*)d_out;
    // 32 images * (12544/32 = 392) spatial tiles = 12544 blocks, 256 threads each.
    crelu_percent_kernel<<<12544, 256>>>(x, out);
}

// round 8
// speedup vs baseline: 1.1093x; 1.0870x over previous
#include <cuda_runtime.h>
#include <cstdint>

// cReLU_percent: x (32, 128, 112, 112) fp32, PERCENT=0.5 -> k=64 of C=128.
// Per pixel (n,h,w): t = 64th largest over channels; out = relu(where(x>=t, x, 0)).
// c = #positives. c < 64 -> t <= 0 -> out = relu(x).
// c >= 64 -> t = (c-63)-th smallest positive (exact warp min-extraction).
// R6: occupancy 4->6 blocks/SM (MLP: 11KB -> 24KB in flight/SM, DRAM saturation);
//     cheaper transform (bits-1 keying) and branch-free duplicate-safe removal.

#define FULLMASK 0xffffffffu

__global__ __launch_bounds__(256, 6)
void crelu_percent_kernel(const float* __restrict__ x, float* __restrict__ out) {
    __shared__ float tile[128][33];   // [channel][pixel], +1 pad: conflict-free both phases
    __shared__ float thr_s[32];

    const int tid  = threadIdx.x;
    const int lane = tid & 31;
    const int warp = tid >> 5;

    // Block -> (image n, spatial offset s0). HW = 112*112 = 12544 = 392 * 32.
    const int nblk = blockIdx.x;            // 0 .. 12543
    const int n    = nblk / 392;
    const int s0   = (nblk - n * 392) << 5; // *32
    const int base = n * (128 * 12544) + s0;

    // ---- Load phase: 4 x LDG.128 per thread, coalesced ----
    const int g   = tid & 7;           // pixel quad within the 32-pixel tile
    const int ch0 = tid >> 3;          // base channel (0..31), +32*i
    float4 v[4];
    #pragma unroll
    for (int i = 0; i < 4; ++i) {
        const int c = ch0 + (i << 5);
        v[i] = *reinterpret_cast<const float4*>(x + base + c * 12544 + (g << 2));
        // STS.32 x4: bank = (c + 4g + j) mod 32 -> distinct across lanes: conflict-free
        tile[c][(g << 2) + 0] = v[i].x;
        tile[c][(g << 2) + 1] = v[i].y;
        tile[c][(g << 2) + 2] = v[i].z;
        tile[c][(g << 2) + 3] = v[i].w;
    }
    __syncthreads();

    // ---- Selection phase: each warp handles 4 pixels ----
    #pragma unroll
    for (int pi = 0; pi < 4; ++pi) {
        const int p = (warp << 2) + pi;

        // Conflict-free gather: bank = (lane + p) mod 32.
        const float a0 = tile[lane      ][p];
        const float a1 = tile[lane + 32 ][p];
        const float a2 = tile[lane + 64 ][p];
        const float a3 = tile[lane + 96 ][p];

        // Key = float_bits - 1 (unsigned): positives order-preserved & small,
        // +0.0 -> 0xFFFFFFFF, -0.0 -> 0x7FFFFFFF, negatives -> >= 0x80000000.
        // Every non-positive key > every positive key (max positive key 0x7F7FFFFE).
        unsigned u0 = __float_as_uint(a0) - 1u;
        unsigned u1 = __float_as_uint(a1) - 1u;
        unsigned u2 = __float_as_uint(a2) - 1u;
        unsigned u3 = __float_as_uint(a3) - 1u;

        const int cnt = (a0 > 0.0f) + (a1 > 0.0f) + (a2 > 0.0f) + (a3 > 0.0f);
        const int c   = __reduce_add_sync(FULLMASK, cnt);   // # positives in pixel

        float thr = 0.0f;                 // c < 64: threshold <= 0 -> out == relu(x)
        if (c >= 64) {
            int m = c - 63;               // threshold = m-th smallest positive
            unsigned wmin;
            for (;;) {
                const unsigned lmin = min(min(u0, u1), min(u2, u3));
                wmin = __reduce_min_sync(FULLMASK, lmin);   // REDUX.UMIN
                if (m == 1) break;                          // common fast exit
                // remove ALL instances of wmin, decrement m by their count (exact)
                const int eq  = (u0 == wmin) + (u1 == wmin) +
                                (u2 == wmin) + (u3 == wmin);
                const int neq = __reduce_add_sync(FULLMASK, eq);
                if (m <= neq) break;                        // wmin is the threshold
                m -= neq;
                if (u0 == wmin) u0 = 0xFFFFFFFFu;
                if (u1 == wmin) u1 = 0xFFFFFFFFu;
                if (u2 == wmin) u2 = 0xFFFFFFFFu;
                if (u3 == wmin) u3 = 0xFFFFFFFFu;
            }
            thr = __uint_as_float(wmin + 1u);   // undo the -1 key transform
        }
        if (lane == 0) thr_s[p] = thr;
    }
    __syncthreads();

    // ---- Output phase: values still in registers; thresholds via broadcast LDS.128 ----
    // thr >= +0.0 always, so (v >= thr ? v : 0) == relu(where(v >= t_true, v, 0)).
    const float4 tq = *reinterpret_cast<const float4*>(&thr_s[g << 2]);
    #pragma unroll
    for (int i = 0; i < 4; ++i) {
        const int c = ch0 + (i << 5);
        float4 o;
        o.x = (v[i].x >= tq.x) ? v[i].x : 0.0f;
        o.y = (v[i].y >= tq.y) ? v[i].y : 0.0f;
        o.z = (v[i].z >= tq.z) ? v[i].z : 0.0f;
        o.w = (v[i].w >= tq.w) ? v[i].w : 0.0f;
        *reinterpret_cast<float4*>(out + base + c * 12544 + (g << 2)) = o;
    }
}

extern "C" void kernel_launch(void* const* d_in, const int* in_sizes, int n_in,
                              void* d_out, int out_size) {
    const float* x = (const float*)d_in[0];
    float* out = (float*)d_out;
    // 32 images * (12544/32 = 392) spatial tiles = 12544 blocks, 256 threads each.
    crelu_percent_kernel<<<12544, 256>>>(x, out);
}

// round 10
// speedup vs baseline: 1.2077x; 1.0887x over previous
#include <cuda_runtime.h>
#include <cstdint>

// cReLU_percent: x (32, 128, 112, 112) fp32, PERCENT=0.5 -> k=64 of C=128.
// Per pixel (n,h,w): t = 64th largest over channels; out = relu(where(x>=t, x, 0)).
// c = #positives. c < 64 -> t <= 0 -> out = relu(x).
// c >= 64 -> t = (c-63)-th smallest positive (exact warp min-extraction).
// R8: 8 blocks/SM (100% occupancy). Registers freed by re-reading values from the
//     smem tile in the epilogue instead of keeping 16 value-regs live all kernel.

#define FULLMASK 0xffffffffu

__global__ __launch_bounds__(256, 8)
void crelu_percent_kernel(const float* __restrict__ x, float* __restrict__ out) {
    __shared__ float tile[128][33];   // [channel][pixel], +1 pad: conflict-free all phases
    __shared__ float thr_s[32];

    const int tid  = threadIdx.x;
    const int lane = tid & 31;
    const int warp = tid >> 5;

    // Block -> (image n, spatial offset s0). HW = 112*112 = 12544 = 392 * 32.
    const int nblk = blockIdx.x;            // 0 .. 12543
    const int n    = nblk / 392;
    const int s0   = (nblk - n * 392) << 5; // *32
    const int base = n * (128 * 12544) + s0;

    const int g    = tid & 7;          // pixel quad within the 32-pixel tile
    const int ch0  = tid >> 3;         // base channel (0..31), +32*i
    const int gofs = base + (g << 2);  // common gmem offset term

    // ---- Load phase: 4 x LDG.128 batched (MLP), then transpose into smem ----
    {
        float4 t0 = *reinterpret_cast<const float4*>(x + gofs + (ch0      ) * 12544);
        float4 t1 = *reinterpret_cast<const float4*>(x + gofs + (ch0 + 32 ) * 12544);
        float4 t2 = *reinterpret_cast<const float4*>(x + gofs + (ch0 + 64 ) * 12544);
        float4 t3 = *reinterpret_cast<const float4*>(x + gofs + (ch0 + 96 ) * 12544);
        // STS.32: bank = (c + 4g + j) mod 32 -> distinct across lanes: conflict-free
        tile[ch0      ][(g << 2) + 0] = t0.x; tile[ch0      ][(g << 2) + 1] = t0.y;
        tile[ch0      ][(g << 2) + 2] = t0.z; tile[ch0      ][(g << 2) + 3] = t0.w;
        tile[ch0 + 32 ][(g << 2) + 0] = t1.x; tile[ch0 + 32 ][(g << 2) + 1] = t1.y;
        tile[ch0 + 32 ][(g << 2) + 2] = t1.z; tile[ch0 + 32 ][(g << 2) + 3] = t1.w;
        tile[ch0 + 64 ][(g << 2) + 0] = t2.x; tile[ch0 + 64 ][(g << 2) + 1] = t2.y;
        tile[ch0 + 64 ][(g << 2) + 2] = t2.z; tile[ch0 + 64 ][(g << 2) + 3] = t2.w;
        tile[ch0 + 96 ][(g << 2) + 0] = t3.x; tile[ch0 + 96 ][(g << 2) + 1] = t3.y;
        tile[ch0 + 96 ][(g << 2) + 2] = t3.z; tile[ch0 + 96 ][(g << 2) + 3] = t3.w;
    }
    __syncthreads();

    // ---- Selection phase: each warp handles 4 pixels ----
    #pragma unroll
    for (int pi = 0; pi < 4; ++pi) {
        const int p = (warp << 2) + pi;

        // Conflict-free gather: bank = (lane + p) mod 32.
        const float a0 = tile[lane      ][p];
        const float a1 = tile[lane + 32 ][p];
        const float a2 = tile[lane + 64 ][p];
        const float a3 = tile[lane + 96 ][p];

        // Key = float_bits - 1 (unsigned): positives order-preserved & smallest,
        // +0.0 -> 0xFFFFFFFF, -0.0 -> 0x7FFFFFFF, negatives -> >= 0x80000000:
        // every non-positive key > every positive key (max positive 0x7F7FFFFE).
        unsigned u0 = __float_as_uint(a0) - 1u;
        unsigned u1 = __float_as_uint(a1) - 1u;
        unsigned u2 = __float_as_uint(a2) - 1u;
        unsigned u3 = __float_as_uint(a3) - 1u;

        const int cnt = (a0 > 0.0f) + (a1 > 0.0f) + (a2 > 0.0f) + (a3 > 0.0f);
        const int c   = __reduce_add_sync(FULLMASK, cnt);   // # positives in pixel

        float thr = 0.0f;                 // c < 64: threshold <= 0 -> out == relu(x)
        if (c >= 64) {
            int m = c - 63;               // threshold = m-th smallest positive
            unsigned wmin;
            for (;;) {
                const unsigned lmin = min(min(u0, u1), min(u2, u3));
                wmin = __reduce_min_sync(FULLMASK, lmin);   // REDUX.UMIN
                if (m == 1) break;                          // common fast exit
                // remove ALL instances of wmin, decrement m by their count (exact)
                const int eq  = (u0 == wmin) + (u1 == wmin) +
                                (u2 == wmin) + (u3 == wmin);
                const int neq = __reduce_add_sync(FULLMASK, eq);
                if (m <= neq) break;                        // wmin is the threshold
                m -= neq;
                if (u0 == wmin) u0 = 0xFFFFFFFFu;
                if (u1 == wmin) u1 = 0xFFFFFFFFu;
                if (u2 == wmin) u2 = 0xFFFFFFFFu;
                if (u3 == wmin) u3 = 0xFFFFFFFFu;
            }
            thr = __uint_as_float(wmin + 1u);   // undo the -1 key transform
        }
        if (lane == 0) thr_s[p] = thr;
    }
    __syncthreads();

    // ---- Output phase: re-read values from smem (conflict-free, same banks as store),
    //      thresholds via one broadcast LDS.128. thr >= +0.0 always, so
    //      (v >= thr ? v : 0) == relu(where(v >= t_true, v, 0)).
    const float4 tq = *reinterpret_cast<const float4*>(&thr_s[g << 2]);
    #pragma unroll
    for (int i = 0; i < 4; ++i) {
        const int c = ch0 + (i << 5);
        float4 o;
        o.x = tile[c][(g << 2) + 0];
        o.y = tile[c][(g << 2) + 1];
        o.z = tile[c][(g << 2) + 2];
        o.w = tile[c][(g << 2) + 3];
        o.x = (o.x >= tq.x) ? o.x : 0.0f;
        o.y = (o.y >= tq.y) ? o.y : 0.0f;
        o.z = (o.z >= tq.z) ? o.z : 0.0f;
        o.w = (o.w >= tq.w) ? o.w : 0.0f;
        *reinterpret_cast<float4*>(out + gofs + c * 12544) = o;
    }
}

extern "C" void kernel_launch(void* const* d_in, const int* in_sizes, int n_in,
                              void* d_out, int out_size) {
    const float* x = (const float*)d_in[0];
    float* out = (float*)d_out;
    // 32 images * (12544/32 = 392) spatial tiles = 12544 blocks, 256 threads each.
    crelu_percent_kernel<<<12544, 256>>>(x, out);
}

// round 14
// speedup vs baseline: 1.2708x; 1.0522x over previous
#include <cuda_runtime.h>
#include <cstdint>

// cReLU_percent: x (32, 128, 112, 112) fp32, PERCENT=0.5 -> k=64 of C=128.
// Per pixel (n,h,w): t = 64th largest over channels; out = relu(where(x>=t, x, 0)).
// c = #positives. c < 64 -> t <= 0 -> out = relu(x).
// c >= 64 -> t = (c-63)-th smallest positive (exact warp min-extraction).
// R13: revert to proven [128][33] layout (R10's [32][129] rows are 4-mod-16 bytes ->
//      LDS.128 trap; odd-stride conflict-freedom and 16B alignment are incompatible).
//      Selection slimmed: key-based positive count, ballot+popc instead of REDUX.ADD,
//      per-lane sorted keys so each round is UMIN-reduce + ballot + predicated shift.

#define FULLMASK 0xffffffffu
#define POSLIM   0x7F7FFFFFu   // key < POSLIM  <=>  value > 0   (key = float_bits - 1)

__global__ __launch_bounds__(256, 8)
void crelu_percent_kernel(const float* __restrict__ x, float* __restrict__ out) {
    __shared__ float tile[128][33];   // [channel][pixel], +1 pad: conflict-free all phases
    __shared__ float thr_s[32];

    const int tid  = threadIdx.x;
    const int lane = tid & 31;
    const int warp = tid >> 5;

    // Block -> (image n, spatial offset s0). HW = 112*112 = 12544 = 392 * 32.
    const int nblk = blockIdx.x;            // 0 .. 12543
    const int n    = nblk / 392;
    const int s0   = (nblk - n * 392) << 5; // *32
    const int base = n * (128 * 12544) + s0;

    const int g    = tid & 7;          // pixel quad within the 32-pixel tile
    const int ch0  = tid >> 3;         // base channel (0..31), +32*i
    const int gofs = base + (g << 2);  // common gmem offset term

    // ---- Load phase: 4 x LDG.128 batched (MLP), transpose into smem ----
    // STS.32 bank = (c + 4g + j) mod 32 -> distinct across lanes: conflict-free.
    {
        float4 t0 = *reinterpret_cast<const float4*>(x + gofs + (ch0      ) * 12544);
        float4 t1 = *reinterpret_cast<const float4*>(x + gofs + (ch0 + 32 ) * 12544);
        float4 t2 = *reinterpret_cast<const float4*>(x + gofs + (ch0 + 64 ) * 12544);
        float4 t3 = *reinterpret_cast<const float4*>(x + gofs + (ch0 + 96 ) * 12544);
        const int p0 = g << 2;
        tile[ch0      ][p0 + 0] = t0.x; tile[ch0      ][p0 + 1] = t0.y;
        tile[ch0      ][p0 + 2] = t0.z; tile[ch0      ][p0 + 3] = t0.w;
        tile[ch0 + 32 ][p0 + 0] = t1.x; tile[ch0 + 32 ][p0 + 1] = t1.y;
        tile[ch0 + 32 ][p0 + 2] = t1.z; tile[ch0 + 32 ][p0 + 3] = t1.w;
        tile[ch0 + 64 ][p0 + 0] = t2.x; tile[ch0 + 64 ][p0 + 1] = t2.y;
        tile[ch0 + 64 ][p0 + 2] = t2.z; tile[ch0 + 64 ][p0 + 3] = t2.w;
        tile[ch0 + 96 ][p0 + 0] = t3.x; tile[ch0 + 96 ][p0 + 1] = t3.y;
        tile[ch0 + 96 ][p0 + 2] = t3.z; tile[ch0 + 96 ][p0 + 3] = t3.w;
    }
    __syncthreads();

    // ---- Selection phase: each warp handles 4 pixels ----
    #pragma unroll
    for (int pi = 0; pi < 4; ++pi) {
        const int p = (warp << 2) + pi;

        // Conflict-free gather: bank = (lane + p) mod 32.
        const float a0 = tile[lane      ][p];
        const float a1 = tile[lane + 32 ][p];
        const float a2 = tile[lane + 64 ][p];
        const float a3 = tile[lane + 96 ][p];

        // Key = float_bits - 1 (unsigned): positives order-preserved & smallest;
        // +0.0 -> 0xFFFFFFFF, -0.0 -> 0x7FFFFFFF, negatives -> >= 0x80000000.
        unsigned u0 = __float_as_uint(a0) - 1u;
        unsigned u1 = __float_as_uint(a1) - 1u;
        unsigned u2 = __float_as_uint(a2) - 1u;
        unsigned u3 = __float_as_uint(a3) - 1u;

        // Positive count via ballot+popc (no REDUX on the critical path).
        const int c = __popc(__ballot_sync(FULLMASK, u0 < POSLIM))
                    + __popc(__ballot_sync(FULLMASK, u1 < POSLIM))
                    + __popc(__ballot_sync(FULLMASK, u2 < POSLIM))
                    + __popc(__ballot_sync(FULLMASK, u3 < POSLIM));

        float thr = 0.0f;                 // c < 64: threshold <= 0 -> out == relu(x)
        if (c >= 64) {
            int m = c - 63;               // threshold = m-th smallest positive

            // Sort the lane's 4 keys ascending (5 compare-exchanges).
            unsigned lo, hi;
            lo = min(u0, u1); hi = max(u0, u1); u0 = lo; u1 = hi;
            lo = min(u2, u3); hi = max(u2, u3); u2 = lo; u3 = hi;
            lo = min(u0, u2); hi = max(u0, u2); u0 = lo; u2 = hi;
            lo = min(u1, u3); hi = max(u1, u3); u1 = lo; u3 = hi;
            lo = min(u1, u2); hi = max(u1, u2); u1 = lo; u2 = hi;

            unsigned wmin;
            for (;;) {
                wmin = __reduce_min_sync(FULLMASK, u0);     // REDUX.UMIN on lane-min
                if (m == 1) break;                          // common fast exit
                // Each matching lane removes exactly ONE instance (sorted shift);
                // in-lane duplicates of wmin resurface at u0 next round. Exact.
                const bool e  = (u0 == wmin);
                const int  ne = __popc(__ballot_sync(FULLMASK, e));
                if (m <= ne) break;                         // wmin is the threshold
                m -= ne;
                if (e) { u0 = u1; u1 = u2; u2 = u3; u3 = 0xFFFFFFFFu; }
            }
            thr = __uint_as_float(wmin + 1u);   // undo the -1 key transform
        }
        if (lane == 0) thr_s[p] = thr;
    }
    __syncthreads();

    // ---- Output phase: re-read tile (same conflict-free banks as the store),
    //      thresholds via one broadcast LDS.128. thr >= +0.0 always, so
    //      (v >= thr ? v : 0) == relu(where(v >= t_true, v, 0)).
    const float4 tq = *reinterpret_cast<const float4*>(&thr_s[g << 2]);
    const int p0 = g << 2;
    #pragma unroll
    for (int i = 0; i < 4; ++i) {
        const int c = ch0 + (i << 5);
        float4 o;
        o.x = tile[c][p0 + 0];
        o.y = tile[c][p0 + 1];
        o.z = tile[c][p0 + 2];
        o.w = tile[c][p0 + 3];
        o.x = (o.x >= tq.x) ? o.x : 0.0f;
        o.y = (o.y >= tq.y) ? o.y : 0.0f;
        o.z = (o.z >= tq.z) ? o.z : 0.0f;
        o.w = (o.w >= tq.w) ? o.w : 0.0f;
        *reinterpret_cast<float4*>(out + gofs + c * 12544) = o;
    }
}

extern "C" void kernel_launch(void* const* d_in, const int* in_sizes, int n_in,
                              void* d_out, int out_size) {
    const float* x = (const float*)d_in[0];
    float* out = (float*)d_out;
    // 32 images * (12544/32 = 392) spatial tiles = 12544 blocks, 256 threads each.
    crelu_percent_kernel<<<12544, 256>>>(x, out);
}

// round 17
// speedup vs baseline: 1.2813x; 1.0083x over previous
#include <cuda_runtime.h>
#include <cstdint>

// cReLU_percent: x (32, 128, 112, 112) fp32, PERCENT=0.5 -> k=64 of C=128.
// Per pixel (n,h,w): t = 64th largest over channels; out = relu(where(x>=t, x, 0)).
// c = #positives. c < 64 -> t <= 0 -> out = relu(x).
// c >= 64 -> t = (c-63)-th smallest positive (exact warp min-extraction).
// R14: XOR-swizzled [pixel][128] tile (quad granularity, q_phys = q_log ^ (p>>2)):
//      16B alignment preserved -> selection gather is 4x LDS.128, all phases
//      conflict-free. Positive count via one REDUX.ADD. ~-16% issue count.

#define FULLMASK 0xffffffffu
#define POSLIM   0x7F7FFFFFu   // key < POSLIM  <=>  value > 0   (key = float_bits - 1)

__global__ __launch_bounds__(256, 8)
void crelu_percent_kernel(const float* __restrict__ x, float* __restrict__ out) {
    __shared__ __align__(16) float tile[32][128]; // [pixel][swizzled channel]
    __shared__ __align__(16) float thr_s[32];

    const int tid  = threadIdx.x;
    const int lane = tid & 31;
    const int warp = tid >> 5;

    // Block -> (image n, spatial offset s0). HW = 112*112 = 12544 = 392 * 32.
    const int nblk = blockIdx.x;            // 0 .. 12543
    const int n    = nblk / 392;
    const int s0   = (nblk - n * 392) << 5; // *32
    const int base = n * (128 * 12544) + s0;

    const int g    = tid & 7;          // pixel quad within the 32-pixel tile
    const int ch0  = tid >> 3;         // base channel (0..31), +32*i
    const int gofs = base + (g << 2);  // common gmem offset term
    const int p0   = g << 2;

    // Swizzle: channel quad q_log of pixel p lives at physical quad q_log ^ (p>>2).
    // For this thread: q_log = (ch0>>2) + 8i = warp + 8i, p>>2 = g for all 4 pixels,
    // so physical column = 4*(warp^g) + (ch0&3) + 32*i.
    const int colbase = ((warp ^ g) << 2) + (ch0 & 3);

    // ---- Load phase: 4 x LDG.128 batched (MLP), swizzled transpose-scatter ----
    // STS.32 bank = (4*(warp^g) + (ch0&3)) mod 32: (g x ch0&3) -> 32 distinct. CF.
    {
        float4 t0 = *reinterpret_cast<const float4*>(x + gofs + (ch0      ) * 12544);
        float4 t1 = *reinterpret_cast<const float4*>(x + gofs + (ch0 + 32 ) * 12544);
        float4 t2 = *reinterpret_cast<const float4*>(x + gofs + (ch0 + 64 ) * 12544);
        float4 t3 = *reinterpret_cast<const float4*>(x + gofs + (ch0 + 96 ) * 12544);
        tile[p0 + 0][colbase      ] = t0.x; tile[p0 + 1][colbase      ] = t0.y;
        tile[p0 + 2][colbase      ] = t0.z; tile[p0 + 3][colbase      ] = t0.w;
        tile[p0 + 0][colbase + 32 ] = t1.x; tile[p0 + 1][colbase + 32 ] = t1.y;
        tile[p0 + 2][colbase + 32 ] = t1.z; tile[p0 + 3][colbase + 32 ] = t1.w;
        tile[p0 + 0][colbase + 64 ] = t2.x; tile[p0 + 1][colbase + 64 ] = t2.y;
        tile[p0 + 2][colbase + 64 ] = t2.z; tile[p0 + 3][colbase + 64 ] = t2.w;
        tile[p0 + 0][colbase + 96 ] = t3.x; tile[p0 + 1][colbase + 96 ] = t3.y;
        tile[p0 + 2][colbase + 96 ] = t3.z; tile[p0 + 3][colbase + 96 ] = t3.w;
    }
    __syncthreads();

    // ---- Selection phase: warp handles pixels 4*warp..4*warp+3; lane owns
    //      channel quad 'lane', stored at physical quad lane^warp (p>>2 == warp).
    const int qsel = (lane ^ warp) << 2;
    #pragma unroll
    for (int pi = 0; pi < 4; ++pi) {
        const int p = (warp << 2) + pi;

        // One LDS.128 per lane; per phase banks 4*((lane&7)^warp)+j cover all 32. CF.
        const float4 a = *reinterpret_cast<const float4*>(&tile[p][qsel]);

        // Key = float_bits - 1 (unsigned): positives order-preserved & smallest;
        // +0.0 -> 0xFFFFFFFF, -0.0 -> 0x7FFFFFFF, negatives -> >= 0x80000000.
        unsigned u0 = __float_as_uint(a.x) - 1u;
        unsigned u1 = __float_as_uint(a.y) - 1u;
        unsigned u2 = __float_as_uint(a.z) - 1u;
        unsigned u3 = __float_as_uint(a.w) - 1u;

        const int cnt = (u0 < POSLIM) + (u1 < POSLIM) + (u2 < POSLIM) + (u3 < POSLIM);
        const int c   = __reduce_add_sync(FULLMASK, cnt);   // # positives in pixel

        float thr = 0.0f;                 // c < 64: threshold <= 0 -> out == relu(x)
        if (c >= 64) {
            int m = c - 63;               // threshold = m-th smallest positive

            // Sort the lane's 4 keys ascending (5 compare-exchanges).
            unsigned lo, hi;
            lo = min(u0, u1); hi = max(u0, u1); u0 = lo; u1 = hi;
            lo = min(u2, u3); hi = max(u2, u3); u2 = lo; u3 = hi;
            lo = min(u0, u2); hi = max(u0, u2); u0 = lo; u2 = hi;
            lo = min(u1, u3); hi = max(u1, u3); u1 = lo; u3 = hi;
            lo = min(u1, u2); hi = max(u1, u2); u1 = lo; u2 = hi;

            unsigned wmin;
            for (;;) {
                wmin = __reduce_min_sync(FULLMASK, u0);     // REDUX.UMIN on lane-min
                if (m == 1) break;                          // common fast exit
                // Each matching lane removes exactly ONE instance (sorted shift);
                // in-lane duplicates of wmin resurface at u0 next round. Exact.
                const bool e  = (u0 == wmin);
                const int  ne = __popc(__ballot_sync(FULLMASK, e));
                if (m <= ne) break;                         // wmin is the threshold
                m -= ne;
                if (e) { u0 = u1; u1 = u2; u2 = u3; u3 = 0xFFFFFFFFu; }
            }
            thr = __uint_as_float(wmin + 1u);   // undo the -1 key transform
        }
        if (lane == 0) thr_s[p] = thr;
    }
    __syncthreads();

    // ---- Output phase: re-read tile at the exact store addresses (CF mirror),
    //      thresholds via one broadcast LDS.128. thr >= +0.0 always, so
    //      (v >= thr ? v : 0) == relu(where(v >= t_true, v, 0)).
    const float4 tq = *reinterpret_cast<const float4*>(&thr_s[p0]);
    #pragma unroll
    for (int i = 0; i < 4; ++i) {
        const int c   = ch0 + (i << 5);
        const int col = colbase + (i << 5);
        float4 o;
        o.x = tile[p0 + 0][col];
        o.y = tile[p0 + 1][col];
        o.z = tile[p0 + 2][col];
        o.w = tile[p0 + 3][col];
        o.x = (o.x >= tq.x) ? o.x : 0.0f;
        o.y = (o.y >= tq.y) ? o.y : 0.0f;
        o.z = (o.z >= tq.z) ? o.z : 0.0f;
        o.w = (o.w >= tq.w) ? o.w : 0.0f;
        *reinterpret_cast<float4*>(out + gofs + c * 12544) = o;
    }
}

extern "C" void kernel_launch(void* const* d_in, const int* in_sizes, int n_in,
                              void* d_out, int out_size) {
    const float* x = (const float*)d_in[0];
    float* out = (float*)d_out;
    // 32 images * (12544/32 = 392) spatial tiles = 12544 blocks, 256 threads each.
    crelu_percent_kernel<<<12544, 256>>>(x, out);
}